// round 15
// baseline (speedup 1.0000x reference)
#include <cuda_runtime.h>
#include <cstdint>

typedef unsigned long long ull;

#define T_SEQ  1024
#define NTHR   256

__device__ __forceinline__ ull pk2(float lo, float hi) {
    ull r; asm("mov.b64 %0,{%1,%2};" : "=l"(r) : "f"(lo), "f"(hi)); return r;
}
__device__ __forceinline__ float sum2(ull v) {
    float lo, hi; asm("mov.b64 {%0,%1},%2;" : "=f"(lo), "=f"(hi) : "l"(v));
    return lo + hi;
}
__device__ __forceinline__ ull f2fma(ull a, ull b, ull c) {
    ull d; asm("fma.rn.f32x2 %0,%1,%2,%3;" : "=l"(d) : "l"(a), "l"(b), "l"(c)); return d;
}
__device__ __forceinline__ ull f2add(ull a, ull b) {
    ull d; asm("add.rn.f32x2 %0,%1,%2;" : "=l"(d) : "l"(a), "l"(b)); return d;
}
__device__ __forceinline__ float ex2_(float x) {
    float r; asm("ex2.approx.f32 %0,%1;" : "=f"(r) : "f"(x)); return r;
}
__device__ __forceinline__ float rcp_(float x) {
    float r; asm("rcp.approx.f32 %0,%1;" : "=f"(r) : "f"(x)); return r;
}
// short tanh for the A-phase critical chain: 5 inst, ~40 cyc
// tanh(x) = 2/(1+2^(-2x*log2 e)) - 1 ; ex2 saturates to inf/0 at |x| large
__device__ __forceinline__ float tanh5(float x) {
    return fmaf(2.0f, rcp_(1.0f + ex2_(-2.8853900817779268f * x)), -1.0f);
}
// unified gate activation (P-phase): s=1 -> sigmoid, s=2 -> tanh
__device__ __forceinline__ float act_unified(float v, float s) {
    float e = __expf(-s * v);
    return __fdividef(s, 1.0f + e) - (s - 1.0f);
}

struct __align__(16) SMem {
    float4 xbuf[2][7];       // double-buffered x_t
    float  hs[7][64];        // [0..29]=h1(+2 pad=0), [32..61]=h2(+2 pad=0)
    float  act1[7][120];     // interleaved [u*4+g], layer-1 gates for step t+1
    float  act2[7][120];     // interleaved [u*4+g], layer-2 gates for step t
};

template<int NB>
__device__ __forceinline__ void run_body(
    const float* __restrict__ input,
    const float* __restrict__ Wih1, const float* __restrict__ bih1,
    const float* __restrict__ Whh1, const float* __restrict__ bhh1,
    const float* __restrict__ Wih2, const float* __restrict__ bih2,
    const float* __restrict__ Whh2, const float* __restrict__ bhh2,
    const float* __restrict__ Wlin, const float* __restrict__ blin,
    float* __restrict__ out, SMem& sm, int b0)
{
    const int tid  = threadIdx.x;
    const int w    = tid >> 5;
    const int l    = tid & 31;
    const int r    = l & 15;          // row index within warp (valid < 15)
    const int half = l >> 4;          // 0: k in [0,16), 1: k in [16,30)

    const int  jraw = w * 15 + r;
    const int  j    = (jraw < 120) ? jraw : 119;   // clamp (lane r==15)
    const int  g    = j / 30, u = j % 30;
    const bool valid = (r < 15);
    const float sgate = (g == 2) ? 2.0f : 1.0f;    // tanh for g-gate else sigmoid

    // ---- k-split weights, uniform register layout ----
    const int k0 = half * 16;
    ull wx0 = 0, wx1 = 0, wh[8], wa[8], wb[8], bias1 = 0, bias2 = 0;
    if (half == 0) {
        wx0 = pk2(Wih1[j * 4 + 0], Wih1[j * 4 + 1]);
        wx1 = pk2(Wih1[j * 4 + 2], Wih1[j * 4 + 3]);
        bias1 = pk2(bih1[j] + bhh1[j], 0.0f);
        bias2 = pk2(bih2[j] + bhh2[j], 0.0f);
    }
#pragma unroll
    for (int p = 0; p < 8; p++) {
        int k = k0 + 2 * p;
        bool ok = (k + 1 < 30);      // pair 15 (k=30,31) is pad
        wh[p] = ok ? pk2(Whh1[j * 30 + k], Whh1[j * 30 + k + 1]) : 0ull;
        wa[p] = ok ? pk2(Wih2[j * 30 + k], Wih2[j * 30 + k + 1]) : 0ull;
        wb[p] = ok ? pk2(Whh2[j * 30 + k], Whh2[j * 30 + k + 1]) : 0ull;
    }

    // ---- LIN lane assignment: lane l -> output d=l&3, units [ubase, ubase+4) ----
    const int dl    = l & 3;
    const int ubase = (l >> 2) * 4;   // 0,4,...,28
    float wlv0 = (ubase + 0 < 30) ? Wlin[dl * 30 + ubase + 0] : 0.0f;
    float wlv1 = (ubase + 1 < 30) ? Wlin[dl * 30 + ubase + 1] : 0.0f;
    float wlv2 = (ubase + 2 < 30) ? Wlin[dl * 30 + ubase + 2] : 0.0f;
    float wlv3 = (ubase + 3 < 30) ? Wlin[dl * 30 + ubase + 3] : 0.0f;
    const float blin_d = blin[dl];

    // thread-invariant act-store destination: half0 -> act1, half1 -> act2
    float* const dstb = (half ? &sm.act2[0][0] : &sm.act1[0][0]) + (u * 4 + g);

    // ---- shared init ----
    for (int idx = tid; idx < 7 * 64; idx += NTHR) sm.hs[idx >> 6][idx & 63] = 0.0f;
    if (l == 15 && w < NB) {
        sm.xbuf[0][w] = *(const float4*)(input + ((size_t)(b0 + w) * T_SEQ + 0) * 4);
        sm.xbuf[1][w] = *(const float4*)(input + ((size_t)(b0 + w) * T_SEQ + 1) * 4);
    }
    __syncthreads();

    float c1 = 0.0f, c2 = 0.0f;    // warp w owns batch w, lane l = unit

    // ---- prologue: act1(0) from x(0) (h == 0) ----
    {
#pragma unroll
        for (int b = 0; b < NB; b++) {
            ulonglong2 xv = *(const ulonglong2*)&sm.xbuf[0][b];
            ull P1 = f2fma(wx0, xv.x, bias1);
            P1     = f2fma(wx1, xv.y, P1);
            float p1 = sum2(P1);
            float o1 = __shfl_xor_sync(0xffffffffu, p1, 16);
            float a  = act_unified(p1 + o1, sgate);
            if (valid && half == 0) dstb[b * 120] = a;
        }
    }
    __syncthreads();
    if (w < NB && l < 30) {
        float4 A1 = *(const float4*)&sm.act1[w][l * 4];     // i,f,g,o
        c1 = A1.x * A1.z;
        sm.hs[w][l] = A1.w * tanh5(c1);
    }
    __syncthreads();

    // ================= main loop: 2 barriers/step =================
#pragma unroll 1
    for (int t = 0; t < T_SEQ; t++) {
        const int nxt = (t + 1) & 1;

        // ---- P: partials for G1(t+1) and G2(t); 1-shfl combine; act fused ----
#pragma unroll
        for (int b = 0; b < NB; b++) {
            const ulonglong2* hp = (const ulonglong2*)sm.hs[b];
            ulonglong2 xv = *(const ulonglong2*)&sm.xbuf[nxt][b];
            ulonglong2 H0 = hp[half * 4 + 0], H1 = hp[half * 4 + 1];
            ulonglong2 H2 = hp[half * 4 + 2], H3 = hp[half * 4 + 3];
            ulonglong2 K0 = hp[8 + half * 4 + 0], K1 = hp[8 + half * 4 + 1];
            ulonglong2 K2 = hp[8 + half * 4 + 2], K3 = hp[8 + half * 4 + 3];

            ull P1 = f2fma(wx0, xv.x, bias1);
            P1     = f2fma(wx1, xv.y, P1);
            P1 = f2fma(wh[0], H0.x, P1); P1 = f2fma(wh[1], H0.y, P1);
            P1 = f2fma(wh[2], H1.x, P1); P1 = f2fma(wh[3], H1.y, P1);
            P1 = f2fma(wh[4], H2.x, P1); P1 = f2fma(wh[5], H2.y, P1);
            P1 = f2fma(wh[6], H3.x, P1); P1 = f2fma(wh[7], H3.y, P1);

            ull P2a = f2fma(wa[0], H0.x, bias2);
            P2a = f2fma(wa[1], H0.y, P2a);
            P2a = f2fma(wa[2], H1.x, P2a); P2a = f2fma(wa[3], H1.y, P2a);
            P2a = f2fma(wa[4], H2.x, P2a); P2a = f2fma(wa[5], H2.y, P2a);
            P2a = f2fma(wa[6], H3.x, P2a); P2a = f2fma(wa[7], H3.y, P2a);

            ull P2b = 0;
            P2b = f2fma(wb[0], K0.x, P2b); P2b = f2fma(wb[1], K0.y, P2b);
            P2b = f2fma(wb[2], K1.x, P2b); P2b = f2fma(wb[3], K1.y, P2b);
            P2b = f2fma(wb[4], K2.x, P2b); P2b = f2fma(wb[5], K2.y, P2b);
            P2b = f2fma(wb[6], K3.x, P2b); P2b = f2fma(wb[7], K3.y, P2b);

            float p1 = sum2(P1);
            float p2 = sum2(f2add(P2a, P2b));
            // partner-exchange: send the partial the other half needs
            float send = half ? p1 : p2;
            float keep = half ? p2 : p1;
            float recv = __shfl_xor_sync(0xffffffffu, send, 16);
            float a = act_unified(keep + recv, sgate);
            if (valid) dstb[b * 120] = a;
        }
        // x prefetch by spare lane (r == 15, half 0 of batch-warps)
        if (l == 15 && w < NB && t + 2 < T_SEQ)
            sm.xbuf[t & 1][w] =
                *(const float4*)(input + ((size_t)(b0 + w) * T_SEQ + (t + 2)) * 4);
        __syncthreads();

        // ---- A: layer-2 first, then LIN overlapping layer-1 chain ----
        if (w < NB) {
            float4 A2, A1;
            if (l < 30) {
                A2 = *(const float4*)&sm.act2[w][l * 4];   // i,f,g,o
                A1 = *(const float4*)&sm.act1[w][l * 4];
                c2 = A2.y * c2 + A2.x * A2.z;
                sm.hs[w][32 + l] = A2.w * tanh5(c2);
            }
            __syncwarp();
            // LIN(t): lane l -> output d=l&3 over units [ubase, ubase+4);
            // pads (units 30,31) are zero in both hs and wlv.
            float4 hv = *(const float4*)&sm.hs[w][32 + ubase];
            float p = hv.x * wlv0;
            p = fmaf(hv.y, wlv1, p);
            p = fmaf(hv.z, wlv2, p);
            p = fmaf(hv.w, wlv3, p);
            // layer-1 chain interleaves with LIN's shfl latency
            if (l < 30) {
                c1 = A1.y * c1 + A1.x * A1.z;
                sm.hs[w][l] = A1.w * tanh5(c1);
            }
            p += __shfl_xor_sync(0xffffffffu, p, 4);
            p += __shfl_xor_sync(0xffffffffu, p, 8);
            p += __shfl_xor_sync(0xffffffffu, p, 16);
            if (l < 4)
                out[((size_t)(b0 + w) * T_SEQ + t) * 4 + l] = p + blin_d;
        }
        __syncthreads();
        // t = T_SEQ-1 computes act1/h1 for step T_SEQ from stale x — finite,
        // never consumed.
    }
}

__global__ void __launch_bounds__(NTHR, 2)
lstm2_kernel(const float* __restrict__ input,
             const float* __restrict__ Wih1, const float* __restrict__ bih1,
             const float* __restrict__ Whh1, const float* __restrict__ bhh1,
             const float* __restrict__ Wih2, const float* __restrict__ bih2,
             const float* __restrict__ Whh2, const float* __restrict__ bhh2,
             const float* __restrict__ Wlin, const float* __restrict__ blin,
             float* __restrict__ out)
{
    __shared__ SMem sm;
    // 296 CTAs = 2/SM; bids s and s+148 co-locate. Per-SM nb {7,7} (s<124)
    // or {7,6}: 124*14 + 24*13 = 2048.
    const int s = blockIdx.x % 148, wq = blockIdx.x / 148;
    int nb, b0;
    if (s < 124) { b0 = s * 14 + wq * 7;                    nb = 7; }
    else         { b0 = 1736 + (s - 124) * 13 + wq * 7;     nb = (wq == 0) ? 7 : 6; }

    if (nb == 7)
        run_body<7>(input, Wih1, bih1, Whh1, bhh1, Wih2, bih2, Whh2, bhh2,
                    Wlin, blin, out, sm, b0);
    else
        run_body<6>(input, Wih1, bih1, Whh1, bhh1, Wih2, bih2, Whh2, bhh2,
                    Wlin, blin, out, sm, b0);
}

extern "C" void kernel_launch(void* const* d_in, const int* in_sizes, int n_in,
                              void* d_out, int out_size)
{
    const float* input = (const float*)d_in[0];
    const float* Wih1  = (const float*)d_in[1];
    const float* bih1  = (const float*)d_in[2];
    const float* Whh1  = (const float*)d_in[3];
    const float* bhh1  = (const float*)d_in[4];
    const float* Wih2  = (const float*)d_in[5];
    const float* bih2  = (const float*)d_in[6];
    const float* Whh2  = (const float*)d_in[7];
    const float* bhh2  = (const float*)d_in[8];
    const float* Wlin  = (const float*)d_in[9];
    const float* blin  = (const float*)d_in[10];
    float* out = (float*)d_out;

    lstm2_kernel<<<296, NTHR>>>(input, Wih1, bih1, Whh1, bhh1,
                                Wih2, bih2, Whh2, bhh2, Wlin, blin, out);
}

// round 16
// speedup vs baseline: 1.0131x; 1.0131x over previous
#include <cuda_runtime.h>
#include <cstdint>

typedef unsigned long long ull;

#define T_SEQ  1024
#define NTHR   256

__device__ __forceinline__ ull pk2(float lo, float hi) {
    ull r; asm("mov.b64 %0,{%1,%2};" : "=l"(r) : "f"(lo), "f"(hi)); return r;
}
__device__ __forceinline__ float sum2(ull v) {
    float lo, hi; asm("mov.b64 {%0,%1},%2;" : "=f"(lo), "=f"(hi) : "l"(v));
    return lo + hi;
}
__device__ __forceinline__ ull f2fma(ull a, ull b, ull c) {
    ull d; asm("fma.rn.f32x2 %0,%1,%2,%3;" : "=l"(d) : "l"(a), "l"(b), "l"(c)); return d;
}
__device__ __forceinline__ ull f2add(ull a, ull b) {
    ull d; asm("add.rn.f32x2 %0,%1,%2;" : "=l"(d) : "l"(a), "l"(b)); return d;
}
__device__ __forceinline__ float tanhf_fast(float x) {
    float ax = fabsf(x);
    float e  = __expf(ax + ax);
    float r  = 1.0f - __fdividef(2.0f, e + 1.0f);
    return copysignf(r, x);
}
// unified gate activation: s=1 -> sigmoid, s=2 -> tanh
__device__ __forceinline__ float act_unified(float v, float s) {
    float e = __expf(-s * v);
    return __fdividef(s, 1.0f + e) - (s - 1.0f);
}

struct __align__(16) SMem {
    float4 xbuf[2][7];       // double-buffered x_t
    float  hs[7][64];        // [0..29]=h1(+2 pad=0), [32..61]=h2(+2 pad=0)
    float  act1[7][120];     // interleaved [u*4+g], layer-1 gates for step t+1
    float  act2[7][120];     // interleaved [u*4+g], layer-2 gates for step t
};

template<int NB>
__device__ __forceinline__ void run_body(
    const float* __restrict__ input,
    const float* __restrict__ Wih1, const float* __restrict__ bih1,
    const float* __restrict__ Whh1, const float* __restrict__ bhh1,
    const float* __restrict__ Wih2, const float* __restrict__ bih2,
    const float* __restrict__ Whh2, const float* __restrict__ bhh2,
    const float* __restrict__ Wlin, const float* __restrict__ blin,
    float* __restrict__ out, SMem& sm, int b0)
{
    const int tid  = threadIdx.x;
    const int w    = tid >> 5;
    const int l    = tid & 31;
    const int r    = l & 15;          // row index within warp (valid < 15)
    const int half = l >> 4;          // 0: k in [0,16), 1: k in [16,30)

    const int  jraw = w * 15 + r;
    const int  j    = (jraw < 120) ? jraw : 119;   // clamp (lane r==15)
    const int  g    = j / 30, u = j % 30;
    const bool valid = (r < 15);
    const float sgate = (g == 2) ? 2.0f : 1.0f;    // tanh for g-gate else sigmoid

    // ---- k-split weights, uniform register layout ----
    const int k0 = half * 16;
    ull wx0 = 0, wx1 = 0, wh[8], wa[8], wb[8], bias1 = 0, bias2 = 0;
    if (half == 0) {
        wx0 = pk2(Wih1[j * 4 + 0], Wih1[j * 4 + 1]);
        wx1 = pk2(Wih1[j * 4 + 2], Wih1[j * 4 + 3]);
        bias1 = pk2(bih1[j] + bhh1[j], 0.0f);
        bias2 = pk2(bih2[j] + bhh2[j], 0.0f);
    }
#pragma unroll
    for (int p = 0; p < 8; p++) {
        int k = k0 + 2 * p;
        bool ok = (k + 1 < 30);      // pair 15 (k=30,31) is pad
        wh[p] = ok ? pk2(Whh1[j * 30 + k], Whh1[j * 30 + k + 1]) : 0ull;
        wa[p] = ok ? pk2(Wih2[j * 30 + k], Wih2[j * 30 + k + 1]) : 0ull;
        wb[p] = ok ? pk2(Whh2[j * 30 + k], Whh2[j * 30 + k + 1]) : 0ull;
    }

    // ---- LIN lane assignment: lane l -> output d=l&3, units [ubase, ubase+4) ----
    const int dl    = l & 3;
    const int ubase = (l >> 2) * 4;   // 0,4,...,28
    float wlv0 = (ubase + 0 < 30) ? Wlin[dl * 30 + ubase + 0] : 0.0f;
    float wlv1 = (ubase + 1 < 30) ? Wlin[dl * 30 + ubase + 1] : 0.0f;
    float wlv2 = (ubase + 2 < 30) ? Wlin[dl * 30 + ubase + 2] : 0.0f;
    float wlv3 = (ubase + 3 < 30) ? Wlin[dl * 30 + ubase + 3] : 0.0f;
    const float blin_d = blin[dl];

    // thread-invariant act-store destination: half0 -> act1, half1 -> act2
    float* const dstb = (half ? &sm.act2[0][0] : &sm.act1[0][0]) + (u * 4 + g);

    // ---- shared init ----
    for (int idx = tid; idx < 7 * 64; idx += NTHR) sm.hs[idx >> 6][idx & 63] = 0.0f;
    if (l == 15 && w < NB) {
        sm.xbuf[0][w] = *(const float4*)(input + ((size_t)(b0 + w) * T_SEQ + 0) * 4);
        sm.xbuf[1][w] = *(const float4*)(input + ((size_t)(b0 + w) * T_SEQ + 1) * 4);
    }
    __syncthreads();

    float c1 = 0.0f, c2 = 0.0f;    // warp w owns batch w, lane l = unit

    // ---- prologue: act1(0) from x(0) (h == 0) ----
    {
#pragma unroll
        for (int b = 0; b < NB; b++) {
            ulonglong2 xv = *(const ulonglong2*)&sm.xbuf[0][b];
            ull P1 = f2fma(wx0, xv.x, bias1);
            P1     = f2fma(wx1, xv.y, P1);
            float p1 = sum2(P1);
            float o1 = __shfl_xor_sync(0xffffffffu, p1, 16);
            float a  = act_unified(p1 + o1, sgate);
            if (valid && half == 0) dstb[b * 120] = a;
        }
    }
    __syncthreads();
    if (w < NB && l < 30) {
        float4 A1 = *(const float4*)&sm.act1[w][l * 4];     // i,f,g,o
        c1 = A1.x * A1.z;
        sm.hs[w][l] = A1.w * tanhf_fast(c1);
    }
    __syncthreads();

    // ================= main loop: unroll-by-2, 2 barriers/step =================
#pragma unroll 1
    for (int tb = 0; tb < T_SEQ; tb += 2) {
#pragma unroll
        for (int par = 0; par < 2; par++) {
            const int t   = tb + par;        // par is compile-time
            const int nxt = par ^ 1;         // compile-time xbuf index

            // ---- P: partials for G1(t+1), G2(t); 1-shfl combine; act fused ----
#pragma unroll
            for (int b = 0; b < NB; b++) {
                const ulonglong2* hp = (const ulonglong2*)sm.hs[b];
                ulonglong2 xv = *(const ulonglong2*)&sm.xbuf[nxt][b];
                ulonglong2 H0 = hp[half * 4 + 0], H1 = hp[half * 4 + 1];
                ulonglong2 H2 = hp[half * 4 + 2], H3 = hp[half * 4 + 3];
                ulonglong2 K0 = hp[8 + half * 4 + 0], K1 = hp[8 + half * 4 + 1];
                ulonglong2 K2 = hp[8 + half * 4 + 2], K3 = hp[8 + half * 4 + 3];

                ull P1 = f2fma(wx0, xv.x, bias1);
                P1     = f2fma(wx1, xv.y, P1);
                P1 = f2fma(wh[0], H0.x, P1); P1 = f2fma(wh[1], H0.y, P1);
                P1 = f2fma(wh[2], H1.x, P1); P1 = f2fma(wh[3], H1.y, P1);
                P1 = f2fma(wh[4], H2.x, P1); P1 = f2fma(wh[5], H2.y, P1);
                P1 = f2fma(wh[6], H3.x, P1); P1 = f2fma(wh[7], H3.y, P1);

                ull P2a = f2fma(wa[0], H0.x, bias2);
                P2a = f2fma(wa[1], H0.y, P2a);
                P2a = f2fma(wa[2], H1.x, P2a); P2a = f2fma(wa[3], H1.y, P2a);
                P2a = f2fma(wa[4], H2.x, P2a); P2a = f2fma(wa[5], H2.y, P2a);
                P2a = f2fma(wa[6], H3.x, P2a); P2a = f2fma(wa[7], H3.y, P2a);

                ull P2b = 0;
                P2b = f2fma(wb[0], K0.x, P2b); P2b = f2fma(wb[1], K0.y, P2b);
                P2b = f2fma(wb[2], K1.x, P2b); P2b = f2fma(wb[3], K1.y, P2b);
                P2b = f2fma(wb[4], K2.x, P2b); P2b = f2fma(wb[5], K2.y, P2b);
                P2b = f2fma(wb[6], K3.x, P2b); P2b = f2fma(wb[7], K3.y, P2b);

                float p1 = sum2(P1);
                float p2 = sum2(f2add(P2a, P2b));
                // partner-exchange: send the partial the other half needs
                float send = half ? p1 : p2;
                float keep = half ? p2 : p1;
                float recv = __shfl_xor_sync(0xffffffffu, send, 16);
                float a = act_unified(keep + recv, sgate);
                if (valid) dstb[b * 120] = a;
            }
            // x prefetch by spare lane (r == 15, half 0 of batch-warps)
            if (l == 15 && w < NB && t + 2 < T_SEQ)
                sm.xbuf[par][w] =
                    *(const float4*)(input + ((size_t)(b0 + w) * T_SEQ + (t + 2)) * 4);
            __syncthreads();

            // ---- A: c2/h2(t) + LIN(t); c1/h1(t+1). warp w = batch w ----
            if (w < NB) {
                if (l < 30) {
                    float4 A2 = *(const float4*)&sm.act2[w][l * 4];   // i,f,g,o
                    float4 A1 = *(const float4*)&sm.act1[w][l * 4];
                    c2  = A2.y * c2 + A2.x * A2.z;
                    c1  = A1.y * c1 + A1.x * A1.z;
                    sm.hs[w][32 + l] = A2.w * tanhf_fast(c2);
                    sm.hs[w][l]      = A1.w * tanhf_fast(c1);
                }
                __syncwarp();
                // LIN(t): lane l -> output d=l&3 over units [ubase, ubase+4);
                // pads (units 30,31) are zero in both hs and wlv.
                float4 hv = *(const float4*)&sm.hs[w][32 + ubase];
                float p = hv.x * wlv0;
                p = fmaf(hv.y, wlv1, p);
                p = fmaf(hv.z, wlv2, p);
                p = fmaf(hv.w, wlv3, p);
                p += __shfl_xor_sync(0xffffffffu, p, 4);
                p += __shfl_xor_sync(0xffffffffu, p, 8);
                p += __shfl_xor_sync(0xffffffffu, p, 16);
                if (l < 4)
                    out[((size_t)(b0 + w) * T_SEQ + t) * 4 + l] = p + blin_d;
            }
            __syncthreads();
            // t = T_SEQ-1 computes act1/h1 for step T_SEQ from stale x — finite,
            // never consumed.
        }
    }
}

__global__ void __launch_bounds__(NTHR, 2)
lstm2_kernel(const float* __restrict__ input,
             const float* __restrict__ Wih1, const float* __restrict__ bih1,
             const float* __restrict__ Whh1, const float* __restrict__ bhh1,
             const float* __restrict__ Wih2, const float* __restrict__ bih2,
             const float* __restrict__ Whh2, const float* __restrict__ bhh2,
             const float* __restrict__ Wlin, const float* __restrict__ blin,
             float* __restrict__ out)
{
    __shared__ SMem sm;
    // 296 CTAs = 2/SM; bids s and s+148 co-locate. Per-SM nb {7,7} (s<124)
    // or {7,6}: 124*14 + 24*13 = 2048.
    const int s = blockIdx.x % 148, wq = blockIdx.x / 148;
    int nb, b0;
    if (s < 124) { b0 = s * 14 + wq * 7;                    nb = 7; }
    else         { b0 = 1736 + (s - 124) * 13 + wq * 7;     nb = (wq == 0) ? 7 : 6; }

    if (nb == 7)
        run_body<7>(input, Wih1, bih1, Whh1, bhh1, Wih2, bih2, Whh2, bhh2,
                    Wlin, blin, out, sm, b0);
    else
        run_body<6>(input, Wih1, bih1, Whh1, bhh1, Wih2, bih2, Whh2, bhh2,
                    Wlin, blin, out, sm, b0);
}

extern "C" void kernel_launch(void* const* d_in, const int* in_sizes, int n_in,
                              void* d_out, int out_size)
{
    const float* input = (const float*)d_in[0];
    const float* Wih1  = (const float*)d_in[1];
    const float* bih1  = (const float*)d_in[2];
    const float* Whh1  = (const float*)d_in[3];
    const float* bhh1  = (const float*)d_in[4];
    const float* Wih2  = (const float*)d_in[5];
    const float* bih2  = (const float*)d_in[6];
    const float* Whh2  = (const float*)d_in[7];
    const float* bhh2  = (const float*)d_in[8];
    const float* Wlin  = (const float*)d_in[9];
    const float* blin  = (const float*)d_in[10];
    float* out = (float*)d_out;

    lstm2_kernel<<<296, NTHR>>>(input, Wih1, bih1, Whh1, bhh1,
                                Wih2, bih2, Whh2, bhh2, Wlin, blin, out);
}